// round 12
// baseline (speedup 1.0000x reference)
#include <cuda_runtime.h>
#include <math_constants.h>

#define N_SRC 100000
#define MROWS 20000
#define KNEI 32
#define HDIM 128
#define WPB 8            // warps per block (main), 1 row per warp
#define NEG_SLOPE 0.01f
#define FULLM 0xffffffffu

// -------- packed block-invariant table (float offsets into g_tab) ----------
#define TAB_R    0                       // 128 f    sorted ratios (desc)
#define TAB_P    128                     // 129 f4   prefix (wlwr,wlbr,blwr,blbr)
#define TAB_F    644                     // 129 f2   prefix (wl*an, bl*an)
#define TAB_WRBR 902                     // 128 f2   permuted (wr,br)
#define TAB_WLBL 1158                    // 128 f2   permuted (wl,bl)
#define TAB_AREF 1414                    // 128 f    permuted a_ref
#define TAB_C12  1542                    // 2  f     (sum wr*aref, sum br*aref)
#define TAB_SIZE 1552                    // padded to /4

__device__ __align__(16) float g_tab[TAB_SIZE];

// exact fp32 warp max via integer redux (monotone order-preserving map)
__device__ __forceinline__ float warp_max_f32(float x) {
    int ix = __float_as_int(x);
    ix = (ix >= 0) ? ix : (ix ^ 0x7fffffff);
    int mi;
    asm("redux.sync.max.s32 %0, %1, 0xffffffff;" : "=r"(mi) : "r"(ix));
    return __int_as_float((mi >= 0) ? mi : (mi ^ 0x7fffffff));
}

// ---------------------------------------------------------------------------
// Prep kernel: 1 block, 128 threads. Sort j by r = bl/wl descending, build
// all prefix tables, write the 6.2KB packed table to g_tab.
// ---------------------------------------------------------------------------
__global__ void prep_kernel(const float* __restrict__ wl_g, const float* __restrict__ bl_g,
                            const float* __restrict__ wr_g, const float* __restrict__ br_g,
                            const float* __restrict__ att_inter) {
    __shared__ __align__(16) float s_rraw[HDIM];
    __shared__ float4 s_scat4[HDIM];
    __shared__ float2 s_scat2[HDIM];
    __shared__ float  s_wt[4][6];
    __shared__ float  s_cw[4][2];

    const int tid = threadIdx.x, warp = tid >> 5, lane = tid & 31;

    float pw  = wl_g[tid],  pb  = bl_g[tid];
    float pwr = wr_g[tid],  pbr = br_g[tid];
    float par = att_inter[tid];
    float an  = att_inter[HDIM + tid];
    float r;
    if (pw > 0.f) r = pb / pw;
    else          r = (pb > 0.f) ? CUDART_INF_F : -CUDART_INF_F;
    s_rraw[tid] = r;
    float cw1 = pwr * par, cw2 = pbr * par;
    __syncthreads();

    // stable descending rank
    const float4* r4 = (const float4*)s_rraw;
    int rank = 0;
    #pragma unroll
    for (int k4 = 0; k4 < HDIM / 4; k4++) {
        float4 q = r4[k4];
        int k = 4 * k4;
        rank += (q.x > r) || (q.x == r && (k + 0) < tid);
        rank += (q.y > r) || (q.y == r && (k + 1) < tid);
        rank += (q.z > r) || (q.z == r && (k + 2) < tid);
        rank += (q.w > r) || (q.w == r && (k + 3) < tid);
    }
    g_tab[TAB_R + rank] = r;
    ((float2*)(g_tab + TAB_WRBR))[rank] = make_float2(pwr, pbr);
    ((float2*)(g_tab + TAB_WLBL))[rank] = make_float2(pw, pb);
    g_tab[TAB_AREF + rank] = par;
    s_scat4[rank] = make_float4(pw * pwr, pw * pbr, pb * pwr, pb * pbr);
    s_scat2[rank] = make_float2(pw * an, pb * an);
    #pragma unroll
    for (int o = 16; o; o >>= 1) {
        cw1 += __shfl_xor_sync(FULLM, cw1, o);
        cw2 += __shfl_xor_sync(FULLM, cw2, o);
    }
    if (lane == 0) { s_cw[warp][0] = cw1; s_cw[warp][1] = cw2; }
    __syncthreads();

    // 6-channel inclusive scan over sorted order
    float4 q4 = s_scat4[tid];
    float2 q2 = s_scat2[tid];
    float a0 = q4.x, a1 = q4.y, a2 = q4.z, a3 = q4.w, a4 = q2.x, a5 = q2.y;
    #pragma unroll
    for (int o = 1; o < 32; o <<= 1) {
        float t0 = __shfl_up_sync(FULLM, a0, o);
        float t1 = __shfl_up_sync(FULLM, a1, o);
        float t2 = __shfl_up_sync(FULLM, a2, o);
        float t3 = __shfl_up_sync(FULLM, a3, o);
        float t4 = __shfl_up_sync(FULLM, a4, o);
        float t5 = __shfl_up_sync(FULLM, a5, o);
        if (lane >= o) { a0 += t0; a1 += t1; a2 += t2; a3 += t3; a4 += t4; a5 += t5; }
    }
    if (lane == 31) {
        s_wt[warp][0] = a0; s_wt[warp][1] = a1; s_wt[warp][2] = a2;
        s_wt[warp][3] = a3; s_wt[warp][4] = a4; s_wt[warp][5] = a5;
    }
    __syncthreads();
    float o0 = 0.f, o1 = 0.f, o2 = 0.f, o3 = 0.f, o4 = 0.f, o5 = 0.f;
    for (int w = 0; w < warp; w++) {
        o0 += s_wt[w][0]; o1 += s_wt[w][1]; o2 += s_wt[w][2];
        o3 += s_wt[w][3]; o4 += s_wt[w][4]; o5 += s_wt[w][5];
    }
    ((float4*)(g_tab + TAB_P))[tid + 1] = make_float4(a0 + o0, a1 + o1, a2 + o2, a3 + o3);
    ((float2*)(g_tab + TAB_F))[tid + 1] = make_float2(a4 + o4, a5 + o5);
    if (tid == 0) {
        ((float4*)(g_tab + TAB_P))[0] = make_float4(0.f, 0.f, 0.f, 0.f);
        ((float2*)(g_tab + TAB_F))[0] = make_float2(0.f, 0.f);
        g_tab[TAB_C12 + 0] = s_cw[0][0] + s_cw[1][0] + s_cw[2][0] + s_cw[3][0];
        g_tab[TAB_C12 + 1] = s_cw[0][1] + s_cw[1][1] + s_cw[2][1] + s_cw[3][1];
        g_tab[TAB_SIZE - 8] = 0.f; g_tab[TAB_SIZE - 7] = 0.f;  // pad deterministic
        g_tab[TAB_SIZE - 6] = 0.f; g_tab[TAB_SIZE - 5] = 0.f;
        g_tab[TAB_SIZE - 4] = 0.f; g_tab[TAB_SIZE - 3] = 0.f;
        g_tab[TAB_SIZE - 2] = 0.f; g_tab[TAB_SIZE - 1] = 0.f;
    }
}

// ---------------------------------------------------------------------------
// Main kernel: 2500 blocks x 256 threads, 1 row per warp. Prologue is just a
// 6.2KB table copy -> high occupancy, latency well hidden.
// ---------------------------------------------------------------------------
__global__ void __launch_bounds__(256) main_kernel(
        const int*   __restrict__ nei,
        const float* __restrict__ h,
        const float* __restrict__ h_refer,
        float* __restrict__ out, float* __restrict__ attOut) {

    __shared__ __align__(16) float s_tab[TAB_SIZE];
    __shared__ float2 s_pref[WPB][HDIM + 1];   // y<0 scan table

    const int tid  = threadIdx.x;
    const int warp = tid >> 5, lane = tid & 31;
    const int m = blockIdx.x * WPB + warp;

    // prefetch row data (overlaps table copy)
    const int   idx = __ldg(&nei[m * KNEI + lane]);
    const float y   = __ldg(&h_refer[m]);
    const float x   = __ldg(&h[idx]);           // 400KB table, L2-resident

    // copy block-invariant tables (2 float4 per thread)
    {
        float4* dst = (float4*)s_tab;
        const float4* src = (const float4*)g_tab;
        #pragma unroll
        for (int i = tid; i < TAB_SIZE / 4; i += 256) dst[i] = src[i];
    }
    __syncthreads();

    const float*  s_r    = s_tab + TAB_R;
    const float4* s_P    = (const float4*)(s_tab + TAB_P);
    const float2* s_F    = (const float2*)(s_tab + TAB_F);
    const float2* s_wrbr = (const float2*)(s_tab + TAB_WRBR);
    const float2* s_wlbl = (const float2*)(s_tab + TAB_WLBL);
    const float*  s_aref = s_tab + TAB_AREF;
    const float c1 = s_tab[TAB_C12], c2 = s_tab[TAB_C12 + 1];

    // register pivots for search levels 0-3 (independent LDS, pipelined)
    const float pv127 = s_r[127], pv63 = s_r[63];
    const float pv31 = s_r[31], pv95 = s_r[95];
    const float pv15 = s_r[15], pv47 = s_r[47], pv79 = s_r[79], pv111 = s_r[111];

    // c = #{j : r_j > t}, t = -x  (branchless monobound, 8 probes)
    const float t = -x;
    int c = (pv63 > t) ? 64 : 0;
    c += ((c ? pv95 : pv31) > t) ? 32 : 0;
    float pv3 = (c & 64) ? ((c & 32) ? pv111 : pv79)
                         : ((c & 32) ? pv47  : pv15);
    c += (pv3 > t) ? 16 : 0;
    c += (s_r[c + 7] > t) ? 8 : 0;
    c += (s_r[c + 3] > t) ? 4 : 0;
    c += (s_r[c + 1] > t) ? 2 : 0;
    c += (s_r[c]     > t) ? 1 : 0;
    c = (pv127 > t) ? 128 : c;              // all-active case

    float2 F = s_F[c];
    float f = fmaf(x, F.x, F.y);            // nei_emb . a_nei

    float gp, lr;
    if (y >= 0.f) {
        // hr_j = y*wr_j + br_j exactly -> row-independent tables
        gp = fmaf(y, c1, c2);
        float4 P = s_P[c];
        lr = fmaf(x, fmaf(y, P.x, P.y), fmaf(y, P.z, P.w));
    } else {
        // fallback: 3-channel warp scan (wl*hr, bl*hr, gp)
        float a[4], b[4];
        float gpl = 0.f;
        #pragma unroll
        for (int i = 0; i < 4; i++) {
            int j = lane * 4 + i;
            float2 u = s_wrbr[j];
            float hr = fmaxf(fmaf(y, u.x, u.y), 0.f);
            gpl = fmaf(hr, s_aref[j], gpl);
            float2 w2 = s_wlbl[j];
            a[i] = w2.x * hr;
            b[i] = w2.y * hr;
        }
        a[1] += a[0]; a[2] += a[1]; a[3] += a[2];
        b[1] += b[0]; b[2] += b[1]; b[3] += b[2];
        float ta = a[3], tb = b[3], tg = gpl;
        #pragma unroll
        for (int o = 1; o < 32; o <<= 1) {
            float va = __shfl_up_sync(FULLM, ta, o);
            float vb = __shfl_up_sync(FULLM, tb, o);
            float vg = __shfl_up_sync(FULLM, tg, o);
            if (lane >= o) { ta += va; tb += vb; tg += vg; }
        }
        gp = __shfl_sync(FULLM, tg, 31);            // full gp sum
        float oa = ta - a[3], ob = tb - b[3];
        if (lane == 0) s_pref[warp][0] = make_float2(0.f, 0.f);
        #pragma unroll
        for (int i = 0; i < 4; i++)
            s_pref[warp][lane * 4 + i + 1] = make_float2(oa + a[i], ob + b[i]);
        __syncwarp();
        float2 p = s_pref[warp][c];
        lr = fmaf(x, p.x, p.y);
    }

    float logit = gp + f;
    logit = (logit >= 0.f) ? logit : NEG_SLOPE * logit;

    // warp softmax: exact max via integer redux, fused dual-channel sum
    float mx = warp_max_f32(logit);
    float e  = __expf(logit - mx);
    float s0 = e, s1 = e * lr;
    #pragma unroll
    for (int o = 16; o; o >>= 1) {
        s0 += __shfl_xor_sync(FULLM, s0, o);
        s1 += __shfl_xor_sync(FULLM, s1, o);
    }
    float inv;
    asm("rcp.approx.f32 %0, %1;" : "=f"(inv) : "f"(s0));
    attOut[m * KNEI + lane] = e * inv;
    if (lane == 0) out[m] = fmaxf(s1 * inv, 0.f);
}

// ---------------------------------------------------------------------------
extern "C" void kernel_launch(void* const* d_in, const int* in_sizes, int n_in,
                              void* d_out, int out_size) {
    const int*   nei       = (const int*)  d_in[0];
    const float* h         = (const float*)d_in[1];
    const float* h_refer   = (const float*)d_in[2];
    const float* map_l_w   = (const float*)d_in[3];
    const float* map_l_b   = (const float*)d_in[4];
    const float* map_r_w   = (const float*)d_in[5];
    const float* map_r_b   = (const float*)d_in[6];
    const float* att_inter = (const float*)d_in[7];

    float* out    = (float*)d_out;          // [M]
    float* attOut = out + MROWS;            // [M, K]

    prep_kernel<<<1, HDIM>>>(map_l_w, map_l_b, map_r_w, map_r_b, att_inter);
    main_kernel<<<MROWS / WPB, 256>>>(nei, h, h_refer, out, attOut);
}